// round 11
// baseline (speedup 1.0000x reference)
#include <cuda_runtime.h>
#include <cuda_bf16.h>
#include <cuda_fp16.h>
#include <math.h>

// ---------------------------------------------------------------------------
// Problem constants
// ---------------------------------------------------------------------------
#define S_TOK   2048
#define N_TOK   1024
#define D_MODEL 1024
#define H_HEADS 16
#define HD      64
#define D_MLP   4096
#define COND    128
#define BSZ     16

// ---------------------------------------------------------------------------
// Device scratch
// ---------------------------------------------------------------------------
__device__ float  g_mods[6 * D_MODEL];
__device__ __half g_h  [S_TOK * D_MODEL];
__device__ __half g_h2 [S_TOK * D_MODEL];
__device__ __half g_Oh [S_TOK * D_MODEL];
__device__ __half g_m1 [S_TOK * D_MLP];
__device__ __half g_Qh [H_HEADS * S_TOK * HD];   // fp16, pre-scaled by 0.125
__device__ __half g_Kh [H_HEADS * S_TOK * HD];
__device__ __half g_Vt [H_HEADS * HD * S_TOK];   // TRANSPOSED: [head][dim][seq]
__device__ float  g_x2 [S_TOK * D_MODEL];
// fp16 weights (converted once per launch)
__device__ __half g_wq [3 * D_MODEL * D_MODEL];
__device__ __half g_wo [D_MODEL * D_MODEL];
__device__ __half g_w1 [D_MLP * D_MODEL];
__device__ __half g_w2 [D_MODEL * D_MLP];

// ---------------------------------------------------------------------------
// fp32 -> fp16 convert: all four weight arrays in ONE kernel
// ---------------------------------------------------------------------------
#define N4Q (3 * D_MODEL * D_MODEL / 4)
#define N4O (D_MODEL * D_MODEL / 4)
#define N4M (D_MLP * D_MODEL / 4)
#define N4TOT (N4Q + N4O + N4M + N4M)

__global__ void f2h_all(const float* __restrict__ wq, const float* __restrict__ wo,
                        const float* __restrict__ w1, const float* __restrict__ w2) {
    int i = blockIdx.x * blockDim.x + threadIdx.x;
    if (i >= N4TOT) return;
    const float* src;
    __half* dst;
    int off;
    if (i < N4Q)                  { src = wq; dst = g_wq; off = i; }
    else if (i < N4Q + N4O)       { src = wo; dst = g_wo; off = i - N4Q; }
    else if (i < N4Q + N4O + N4M) { src = w1; dst = g_w1; off = i - N4Q - N4O; }
    else                          { src = w2; dst = g_w2; off = i - N4Q - N4O - N4M; }
    float4 v = ((const float4*)src)[off];
    __half2 h0 = __floats2half2_rn(v.x, v.y);
    __half2 h1 = __floats2half2_rn(v.z, v.w);
    ((__half2*)dst)[2 * off]     = h0;
    ((__half2*)dst)[2 * off + 1] = h1;
}

// ---------------------------------------------------------------------------
// adaLN
// ---------------------------------------------------------------------------
__global__ void adaln_kernel(const float* __restrict__ c,
                             const float* __restrict__ W,
                             const float* __restrict__ b) {
    __shared__ float cs[COND];
    int tid = threadIdx.x;
    if (tid < COND) cs[tid] = c[tid];
    __syncthreads();
    int i = blockIdx.x * blockDim.x + tid;
    if (i >= 6 * D_MODEL) return;
    const float* w = W + (size_t)i * COND;
    float acc = 0.f;
#pragma unroll 8
    for (int j = 0; j < COND; j++) acc += w[j] * cs[j];
    g_mods[i] = acc + b[i];
}

// ---------------------------------------------------------------------------
// LayerNorm + modulate -> fp16 output
// ---------------------------------------------------------------------------
__inline__ __device__ float warp_reduce_sum(float v) {
#pragma unroll
    for (int o = 16; o > 0; o >>= 1) v += __shfl_xor_sync(0xffffffffu, v, o);
    return v;
}

__global__ void ln_mod_kernel(const float* __restrict__ X,
                              const float* __restrict__ w,
                              const float* __restrict__ sc,
                              const float* __restrict__ sh,
                              __half* __restrict__ out) {
    int row = blockIdx.x;
    const float4* x4 = (const float4*)(X + (size_t)row * D_MODEL);
    int tid = threadIdx.x;
    float4 v = x4[tid];
    float s  = v.x + v.y + v.z + v.w;
    float ss = v.x*v.x + v.y*v.y + v.z*v.z + v.w*v.w;
    __shared__ float red_s[8], red_ss[8];
    s  = warp_reduce_sum(s);
    ss = warp_reduce_sum(ss);
    int wid = tid >> 5, lid = tid & 31;
    if (lid == 0) { red_s[wid] = s; red_ss[wid] = ss; }
    __syncthreads();
    if (wid == 0) {
        float a = (lid < 8) ? red_s[lid]  : 0.f;
        float b = (lid < 8) ? red_ss[lid] : 0.f;
        a = warp_reduce_sum(a);
        b = warp_reduce_sum(b);
        if (lid == 0) { red_s[0] = a; red_ss[0] = b; }
    }
    __syncthreads();
    float mu  = red_s[0] * (1.f / D_MODEL);
    float var = red_ss[0] * (1.f / D_MODEL) - mu * mu;
    float inv = rsqrtf(var + 1e-5f);
    int d0 = tid * 4;
    float vv[4] = {v.x, v.y, v.z, v.w};
    float o[4];
#pragma unroll
    for (int i = 0; i < 4; i++) {
        int d = d0 + i;
        o[i] = (vv[i] - mu) * inv * w[d] * (1.f + sc[d]) + sh[d];
    }
    __half2 h0 = __floats2half2_rn(o[0], o[1]);
    __half2 h1 = __floats2half2_rn(o[2], o[3]);
    *(__half2*)&out[(size_t)row * D_MODEL + d0]     = h0;
    *(__half2*)&out[(size_t)row * D_MODEL + d0 + 2] = h1;
}

// ---------------------------------------------------------------------------
// Common PTX helpers
// ---------------------------------------------------------------------------
__device__ __forceinline__ float gelu_tanh(float x) {
    float x3 = x * x * x;
    return 0.5f * x * (1.f + tanhf(0.7978845608028654f * (x + 0.044715f * x3)));
}

__device__ __forceinline__ void cp16(void* dst, const void* src) {
    unsigned d = (unsigned)__cvta_generic_to_shared(dst);
    asm volatile("cp.async.cg.shared.global [%0], [%1], 16;\n" :: "r"(d), "l"(src));
}

__device__ __forceinline__ void ldsm4(unsigned& r0, unsigned& r1, unsigned& r2, unsigned& r3,
                                      const __half* p) {
    unsigned a = (unsigned)__cvta_generic_to_shared(p);
    asm volatile("ldmatrix.sync.aligned.m8n8.x4.shared.b16 {%0,%1,%2,%3}, [%4];\n"
                 : "=r"(r0), "=r"(r1), "=r"(r2), "=r"(r3) : "r"(a));
}

__device__ __forceinline__ void mma_fp16(float* c, const unsigned* a, const unsigned* b) {
    asm volatile(
        "mma.sync.aligned.m16n8k16.row.col.f32.f16.f16.f32 "
        "{%0,%1,%2,%3}, {%4,%5,%6,%7}, {%8,%9}, {%0,%1,%2,%3};\n"
        : "+f"(c[0]), "+f"(c[1]), "+f"(c[2]), "+f"(c[3])
        : "r"(a[0]), "r"(a[1]), "r"(a[2]), "r"(a[3]), "r"(b[0]), "r"(b[1]));
}

__device__ __forceinline__ unsigned packp(float x, float y) {
    __half2 h = __floats2half2_rn(x, y);
    return *(unsigned*)&h;
}

// ---------------------------------------------------------------------------
// FP16 GEMM: CTA tile 256x128, 256 threads, 8 warps (4x2) each 64x64,
// 3-stage cp.async ring (72KB dynamic smem), one barrier per k-tile.
// A [M,K] fp16 row-major, B [N,K] fp16 row-major.
// smem per stage: A 256x32 halves (16KB) + B 128x32 halves (8KB); chunk
// swizzle chunk' = chunk ^ ((row>>1)&3) (verified conflict-free).
// EPI: 0 qkv+rope -> Qh/Kh fp16 + Vt fp16 transposed, 1 gate*acc+res -> fp32,
//      2 gelu(acc+bias) -> fp16, 3 gate*(acc+bias)+res -> fp32
// ---------------------------------------------------------------------------
#define STG_A  (256 * 32)                 // halves
#define STG_B  (128 * 32)
#define STG_SZ (STG_A + STG_B)            // 12288 halves = 24KB
#define GSMEM  (3 * STG_SZ * 2)           // 73728 bytes

template<int EPI>
__global__ void __launch_bounds__(256)
gemm16(const __half* __restrict__ A, const __half* __restrict__ B,
       void* __restrict__ Cout, int M, int N, int K,
       const float* __restrict__ bias, const float* __restrict__ gate,
       const float* __restrict__ res,
       const float* __restrict__ cosT, const float* __restrict__ sinT,
       __half* __restrict__ Qp, __half* __restrict__ Kp, __half* __restrict__ Vtp) {
    extern __shared__ __align__(128) __half smem[];

    const int m0 = blockIdx.y * 256;
    const int n0 = blockIdx.x * 128;
    const int tid  = threadIdx.x;
    const int lane = tid & 31;
    const int warp = tid >> 5;
    const int wm = (warp >> 1) * 64;     // 0,64,128,192
    const int wn = (warp & 1) * 64;      // 0,64
    const int g  = lane >> 2;
    const int tg = lane & 3;
    const int sr  = tid >> 2;            // 0..63
    const int scn = tid & 3;

    float acc[4][8][4] = {};
    const int nT = K / 32;

    const int lrow = lane & 7;
    const int a_r8 = ((lane >> 3) & 1) * 8;
    const int a_cb = (lane >> 4) & 1;
    const int b_r8 = ((lane >> 4) & 1) * 8;
    const int b_cb = (lane >> 3) & 1;

    auto issue = [&](int b, int k0) {
        __half* sA = smem + b * STG_SZ;
        __half* sB = sA + STG_A;
#pragma unroll
        for (int i = 0; i < 4; i++) {          // A: rows 0..255
            int r  = sr + 64 * i;
            int sw = scn ^ ((r >> 1) & 3);
            cp16(&sA[r * 32 + sw * 8], &A[(size_t)(m0 + r) * K + k0 + scn * 8]);
        }
#pragma unroll
        for (int i = 0; i < 2; i++) {          // B: rows 0..127
            int r  = sr + 64 * i;
            int sw = scn ^ ((r >> 1) & 3);
            cp16(&sB[r * 32 + sw * 8], &B[(size_t)(n0 + r) * K + k0 + scn * 8]);
        }
        asm volatile("cp.async.commit_group;\n");
    };

    issue(0, 0);
    issue(1, 32);

    for (int t = 0; t < nT; t++) {
        if (t + 1 < nT) asm volatile("cp.async.wait_group 1;\n");
        else            asm volatile("cp.async.wait_group 0;\n");
        __syncthreads();   // tile t ready; also licenses overwrite of buf (t+2)%3
        if (t + 2 < nT) issue((t + 2) % 3, (t + 2) * 32);

        const __half* sA = smem + (t % 3) * STG_SZ;
        const __half* sB = sA + STG_A;
#pragma unroll
        for (int kk = 0; kk < 2; kk++) {
            unsigned af[4][4], bf[8][2];
#pragma unroll
            for (int i = 0; i < 4; i++) {
                int mr = wm + i * 16 + lrow + a_r8;
                int ch = 2 * kk + a_cb;
                int sw = ch ^ ((mr >> 1) & 3);
                ldsm4(af[i][0], af[i][1], af[i][2], af[i][3], &sA[mr * 32 + sw * 8]);
            }
#pragma unroll
            for (int jp = 0; jp < 4; jp++) {
                int nr = wn + jp * 16 + lrow + b_r8;
                int ch = 2 * kk + b_cb;
                int sw = ch ^ ((nr >> 1) & 3);
                ldsm4(bf[2*jp][0], bf[2*jp][1], bf[2*jp+1][0], bf[2*jp+1][1],
                      &sB[nr * 32 + sw * 8]);
            }
#pragma unroll
            for (int i = 0; i < 4; i++)
#pragma unroll
                for (int j = 0; j < 8; j++)
                    mma_fp16(acc[i][j], af[i], bf[j]);
        }
    }

    // ---------------- epilogues ----------------
    if (EPI == 0) {
        // qkv + rope: this warp's 64-col block is exactly one (q/k/v, head)
        int colBlock = n0 + wn;
        int qidx = colBlock >> 10;
        int head = (colBlock & 1023) >> 6;
#pragma unroll
        for (int i = 0; i < 4; i++) {
#pragma unroll
            for (int hh = 0; hh < 2; hh++) {
                int row = m0 + wm + i * 16 + g + hh * 8;
                int p = row & (N_TOK - 1);
#pragma unroll
                for (int j = 0; j < 4; j++) {
                    float o1[2], o2[2];
#pragma unroll
                    for (int cc = 0; cc < 2; cc++) {
                        int d = j * 8 + tg * 2 + cc;
                        float x1 = acc[i][j][hh * 2 + cc];
                        float x2 = acc[i][j + 4][hh * 2 + cc];
                        float cs = cosT[p * 32 + d];
                        float sn = sinT[p * 32 + d];
                        o1[cc] = x1 * cs - x2 * sn;
                        o2[cc] = x2 * cs + x1 * sn;
                    }
                    int d0 = j * 8 + tg * 2;
                    if (qidx == 0) {
                        __half* dst = Qp + ((size_t)head * S_TOK + row) * HD;
                        *(__half2*)&dst[d0]      = __floats2half2_rn(o1[0]*0.125f, o1[1]*0.125f);
                        *(__half2*)&dst[d0 + 32] = __floats2half2_rn(o2[0]*0.125f, o2[1]*0.125f);
                    } else if (qidx == 1) {
                        __half* dst = Kp + ((size_t)head * S_TOK + row) * HD;
                        *(__half2*)&dst[d0]      = __floats2half2_rn(o1[0], o1[1]);
                        *(__half2*)&dst[d0 + 32] = __floats2half2_rn(o2[0], o2[1]);
                    } else {
                        __half* dst = Vtp + (size_t)head * HD * S_TOK;
                        dst[(size_t)(d0)      * S_TOK + row] = __float2half(o1[0]);
                        dst[(size_t)(d0 + 1)  * S_TOK + row] = __float2half(o1[1]);
                        dst[(size_t)(d0 + 32) * S_TOK + row] = __float2half(o2[0]);
                        dst[(size_t)(d0 + 33) * S_TOK + row] = __float2half(o2[1]);
                    }
                }
            }
        }
        return;
    }

#pragma unroll
    for (int i = 0; i < 4; i++) {
        int row0 = m0 + wm + i * 16 + g;
#pragma unroll
        for (int j = 0; j < 8; j++) {
            int col = n0 + wn + j * 8 + tg * 2;
#pragma unroll
            for (int hh = 0; hh < 2; hh++) {
                int row = row0 + hh * 8;
                float v0 = acc[i][j][hh * 2 + 0];
                float v1 = acc[i][j][hh * 2 + 1];
                if (EPI == 1) {
                    float* C = (float*)Cout;
                    C[(size_t)row * N + col]     = gate[col] * v0 + res[(size_t)row * N + col];
                    C[(size_t)row * N + col + 1] = gate[col+1] * v1 + res[(size_t)row * N + col + 1];
                } else if (EPI == 2) {
                    __half* C = (__half*)Cout;
                    __half2 hv = __floats2half2_rn(gelu_tanh(v0 + bias[col]),
                                                   gelu_tanh(v1 + bias[col + 1]));
                    *(__half2*)&C[(size_t)row * N + col] = hv;
                } else {
                    float* C = (float*)Cout;
                    C[(size_t)row * N + col]     = gate[col] * (v0 + bias[col]) + res[(size_t)row * N + col];
                    C[(size_t)row * N + col + 1] = gate[col+1] * (v1 + bias[col+1]) + res[(size_t)row * N + col + 1];
                }
            }
        }
    }
}

// ---------------------------------------------------------------------------
// FP16 MMA block-diffusion attention (FlashAttention-2 style), as R9.
// ---------------------------------------------------------------------------
__global__ void __launch_bounds__(128)
attn_kernel(__half* __restrict__ O) {
    __shared__ __half Qs[16 * 64];
    __shared__ __half Ks[2][64 * 64];
    __shared__ __half Vs[2][64 * 64];   // Vt tile: [dim][key]

    const int qb = blockIdx.x;
    const int h  = blockIdx.y;
    const int t  = threadIdx.x;
    const int lane = t & 31;
    const int warp = t >> 5;
    const int g  = lane >> 2;
    const int tg = lane & 3;
    const int lrow = lane & 7;
    const int a_r8 = ((lane >> 3) & 1) * 8;
    const int a_cb = (lane >> 4) & 1;
    const int b_r8 = ((lane >> 4) & 1) * 8;
    const int b_cb = (lane >> 3) & 1;

    const int q0 = qb * 16;
    const __half* Qg = g_Qh + ((size_t)h * S_TOK + q0) * HD;
    const __half* Kg = g_Kh + (size_t)h * S_TOK * HD;
    const __half* Vg = g_Vt + (size_t)h * HD * S_TOK;

    const int t1n  = (qb < 64) ? 1 : 0;
    const int lenB = (qb < 64) ? qb * 16 : (qb - 63) * 16;
    const int nT   = t1n + ((lenB + 63) >> 6);

    auto tile_k0 = [&](int ti) {
        return (t1n && ti == 0) ? q0 : N_TOK + (ti - t1n) * 64;
    };
    auto tile_nv = [&](int ti) {
        return (t1n && ti == 0) ? 16 : min(64, lenB - (ti - t1n) * 64);
    };

    {
        int row = t >> 3, ch = t & 7;
        cp16(&Qs[row * 64 + (ch ^ (row & 7)) * 8], &Qg[row * 64 + ch * 8]);
    }
    auto issueKV = [&](int b, int k0) {
#pragma unroll
        for (int i = 0; i < 4; i++) {
            int idx = t + i * 128;
            int row = idx >> 3, ch = idx & 7;
            int sw  = (ch ^ (row & 7)) * 8;
            int src = min(k0 + row, S_TOK - 1);
            cp16(&Ks[b][row * 64 + sw], &Kg[(size_t)src * HD + ch * 8]);
            cp16(&Vs[b][row * 64 + sw], &Vg[(size_t)row * S_TOK + k0 + ch * 8]);
        }
        asm volatile("cp.async.commit_group;\n");
    };
    issueKV(0, tile_k0(0));

    unsigned aq[4][4];
    float Oacc[2][4] = {};
    float m0run = -INFINITY, m1run = -INFINITY;
    float l0run = 0.f, l1run = 0.f;

    for (int ti = 0; ti < nT; ti++) {
        asm volatile("cp.async.wait_group 0;\n");
        __syncthreads();
        if (ti == 0) {
#pragma unroll
            for (int kb = 0; kb < 4; kb++) {
                int r  = lrow + a_r8;
                int ch = 2 * kb + a_cb;
                ldsm4(aq[kb][0], aq[kb][1], aq[kb][2], aq[kb][3],
                      &Qs[r * 64 + (ch ^ (r & 7)) * 8]);
            }
        }
        if (ti + 1 < nT) issueKV((ti + 1) & 1, tile_k0(ti + 1));

        const __half* sK = Ks[ti & 1];
        const __half* sV = Vs[ti & 1];
        const int nv = tile_nv(ti);

        float sc[8][4] = {};
#pragma unroll
        for (int kb = 0; kb < 4; kb++) {
            unsigned bf[8][2];
#pragma unroll
            for (int pr = 0; pr < 4; pr++) {
                int r  = pr * 16 + lrow + b_r8;
                int ch = 2 * kb + b_cb;
                ldsm4(bf[2*pr][0], bf[2*pr][1], bf[2*pr+1][0], bf[2*pr+1][1],
                      &sK[r * 64 + (ch ^ (r & 7)) * 8]);
            }
#pragma unroll
            for (int nb = 0; nb < 8; nb++)
                mma_fp16(sc[nb], aq[kb], bf[nb]);
        }
#pragma unroll
        for (int nb = 0; nb < 8; nb++)
            if (nb * 8 >= nv) { sc[nb][0] = sc[nb][1] = sc[nb][2] = sc[nb][3] = -INFINITY; }

        float mx0 = -INFINITY, mx1 = -INFINITY;
#pragma unroll
        for (int nb = 0; nb < 8; nb++) {
            mx0 = fmaxf(mx0, fmaxf(sc[nb][0], sc[nb][1]));
            mx1 = fmaxf(mx1, fmaxf(sc[nb][2], sc[nb][3]));
        }
        mx0 = fmaxf(mx0, __shfl_xor_sync(0xffffffffu, mx0, 1));
        mx0 = fmaxf(mx0, __shfl_xor_sync(0xffffffffu, mx0, 2));
        mx1 = fmaxf(mx1, __shfl_xor_sync(0xffffffffu, mx1, 1));
        mx1 = fmaxf(mx1, __shfl_xor_sync(0xffffffffu, mx1, 2));

        float nm0 = fmaxf(m0run, mx0), nm1 = fmaxf(m1run, mx1);
        float c0 = __expf(m0run - nm0), c1 = __expf(m1run - nm1);
        float ts0 = 0.f, ts1 = 0.f;
#pragma unroll
        for (int nb = 0; nb < 8; nb++) {
            sc[nb][0] = __expf(sc[nb][0] - nm0);
            sc[nb][1] = __expf(sc[nb][1] - nm0);
            sc[nb][2] = __expf(sc[nb][2] - nm1);
            sc[nb][3] = __expf(sc[nb][3] - nm1);
            ts0 += sc[nb][0] + sc[nb][1];
            ts1 += sc[nb][2] + sc[nb][3];
        }
        ts0 += __shfl_xor_sync(0xffffffffu, ts0, 1);
        ts0 += __shfl_xor_sync(0xffffffffu, ts0, 2);
        ts1 += __shfl_xor_sync(0xffffffffu, ts1, 1);
        ts1 += __shfl_xor_sync(0xffffffffu, ts1, 2);
        l0run = l0run * c0 + ts0;  m0run = nm0;
        l1run = l1run * c1 + ts1;  m1run = nm1;

        Oacc[0][0] *= c0; Oacc[0][1] *= c0; Oacc[0][2] *= c1; Oacc[0][3] *= c1;
        Oacc[1][0] *= c0; Oacc[1][1] *= c0; Oacc[1][2] *= c1; Oacc[1][3] *= c1;

        unsigned ap[4][4];
#pragma unroll
        for (int kb2 = 0; kb2 < 4; kb2++) {
            ap[kb2][0] = packp(sc[2*kb2][0],   sc[2*kb2][1]);
            ap[kb2][1] = packp(sc[2*kb2][2],   sc[2*kb2][3]);
            ap[kb2][2] = packp(sc[2*kb2+1][0], sc[2*kb2+1][1]);
            ap[kb2][3] = packp(sc[2*kb2+1][2], sc[2*kb2+1][3]);
        }

#pragma unroll
        for (int kb2 = 0; kb2 < 4; kb2++) {
            unsigned bv0[2], bv1[2];
            int r  = warp * 16 + lrow + b_r8;
            int ch = 2 * kb2 + b_cb;
            ldsm4(bv0[0], bv0[1], bv1[0], bv1[1],
                  &sV[r * 64 + (ch ^ (r & 7)) * 8]);
            mma_fp16(Oacc[0], ap[kb2], bv0);
            mma_fp16(Oacc[1], ap[kb2], bv1);
        }
        __syncthreads();
    }

    float inv0 = 1.f / l0run, inv1 = 1.f / l1run;
    int row0 = q0 + g, row1 = q0 + g + 8;
#pragma unroll
    for (int nb2 = 0; nb2 < 2; nb2++) {
        int col = h * HD + warp * 16 + nb2 * 8 + tg * 2;
        *(__half2*)&O[(size_t)row0 * D_MODEL + col] =
            __floats2half2_rn(Oacc[nb2][0] * inv0, Oacc[nb2][1] * inv0);
        *(__half2*)&O[(size_t)row1 * D_MODEL + col] =
            __floats2half2_rn(Oacc[nb2][2] * inv1, Oacc[nb2][3] * inv1);
    }
}

// ---------------------------------------------------------------------------
// kernel_launch
// ---------------------------------------------------------------------------
extern "C" void kernel_launch(void* const* d_in, const int* in_sizes, int n_in,
                              void* d_out, int out_size) {
    const float* x          = (const float*)d_in[0];
    const float* c          = (const float*)d_in[1];
    const float* cosT       = (const float*)d_in[2];
    const float* sinT       = (const float*)d_in[3];
    const float* norm1_w    = (const float*)d_in[4];
    const float* qkv_w      = (const float*)d_in[5];
    const float* attn_out_w = (const float*)d_in[6];
    const float* norm2_w    = (const float*)d_in[7];
    const float* mlp_w1     = (const float*)d_in[8];
    const float* mlp_b1     = (const float*)d_in[9];
    const float* mlp_w2     = (const float*)d_in[10];
    const float* mlp_b2     = (const float*)d_in[11];
    const float* adaLN_w    = (const float*)d_in[12];
    const float* adaLN_b    = (const float*)d_in[13];
    float* out = (float*)d_out;

    float *mods, *x2;
    __half *h, *h2, *Oh, *m1, *Qp, *Kp, *Vtp, *wq, *wo, *w1, *w2;
    cudaGetSymbolAddress((void**)&mods, g_mods);
    cudaGetSymbolAddress((void**)&h,    g_h);
    cudaGetSymbolAddress((void**)&h2,   g_h2);
    cudaGetSymbolAddress((void**)&Oh,   g_Oh);
    cudaGetSymbolAddress((void**)&m1,   g_m1);
    cudaGetSymbolAddress((void**)&Qp,   g_Qh);
    cudaGetSymbolAddress((void**)&Kp,   g_Kh);
    cudaGetSymbolAddress((void**)&Vtp,  g_Vt);
    cudaGetSymbolAddress((void**)&x2,   g_x2);
    cudaGetSymbolAddress((void**)&wq,   g_wq);
    cudaGetSymbolAddress((void**)&wo,   g_wo);
    cudaGetSymbolAddress((void**)&w1,   g_w1);
    cudaGetSymbolAddress((void**)&w2,   g_w2);

    const float* sh_msa = mods + 0 * D_MODEL;
    const float* sc_msa = mods + 1 * D_MODEL;
    const float* g_msa  = mods + 2 * D_MODEL;
    const float* sh_mlp = mods + 3 * D_MODEL;
    const float* sc_mlp = mods + 4 * D_MODEL;
    const float* g_mlp  = mods + 5 * D_MODEL;

    static bool attr_set = false;
    if (!attr_set) {
        cudaFuncSetAttribute(gemm16<0>, cudaFuncAttributeMaxDynamicSharedMemorySize, GSMEM);
        cudaFuncSetAttribute(gemm16<1>, cudaFuncAttributeMaxDynamicSharedMemorySize, GSMEM);
        cudaFuncSetAttribute(gemm16<2>, cudaFuncAttributeMaxDynamicSharedMemorySize, GSMEM);
        cudaFuncSetAttribute(gemm16<3>, cudaFuncAttributeMaxDynamicSharedMemorySize, GSMEM);
        attr_set = true;
    }

    f2h_all<<<(N4TOT + 255) / 256, 256>>>(qkv_w, attn_out_w, mlp_w1, mlp_w2);

    adaln_kernel<<<(6 * D_MODEL + 127) / 128, 128>>>(c, adaLN_w, adaLN_b);

    ln_mod_kernel<<<S_TOK, 256>>>(x, norm1_w, sc_msa, sh_msa, h);

    gemm16<0><<<dim3(3 * D_MODEL / 128, S_TOK / 256), 256, GSMEM>>>(
        h, wq, nullptr, S_TOK, 3 * D_MODEL, D_MODEL,
        nullptr, nullptr, nullptr, cosT, sinT, Qp, Kp, Vtp);

    attn_kernel<<<dim3(S_TOK / 16, H_HEADS), 128>>>(Oh);

    gemm16<1><<<dim3(D_MODEL / 128, S_TOK / 256), 256, GSMEM>>>(
        Oh, wo, x2, S_TOK, D_MODEL, D_MODEL,
        nullptr, g_msa, x, nullptr, nullptr, nullptr, nullptr, nullptr);

    ln_mod_kernel<<<S_TOK, 256>>>(x2, norm2_w, sc_mlp, sh_mlp, h2);

    gemm16<2><<<dim3(D_MLP / 128, S_TOK / 256), 256, GSMEM>>>(
        h2, w1, m1, S_TOK, D_MLP, D_MODEL,
        mlp_b1, nullptr, nullptr, nullptr, nullptr, nullptr, nullptr, nullptr);

    gemm16<3><<<dim3(D_MODEL / 128, S_TOK / 256), 256, GSMEM>>>(
        m1, w2, out, S_TOK, D_MODEL, D_MLP,
        mlp_b2, g_mlp, x2, nullptr, nullptr, nullptr, nullptr, nullptr);
}

// round 12
// speedup vs baseline: 1.4656x; 1.4656x over previous
#include <cuda_runtime.h>
#include <cuda_bf16.h>
#include <cuda_fp16.h>
#include <math.h>

// ---------------------------------------------------------------------------
// Problem constants
// ---------------------------------------------------------------------------
#define S_TOK   2048
#define N_TOK   1024
#define D_MODEL 1024
#define H_HEADS 16
#define HD      64
#define D_MLP   4096
#define COND    128
#define BSZ     16

// ---------------------------------------------------------------------------
// Device scratch
// ---------------------------------------------------------------------------
__device__ float  g_mods[6 * D_MODEL];
__device__ __half g_h  [S_TOK * D_MODEL];
__device__ __half g_h2 [S_TOK * D_MODEL];
__device__ __half g_Oh [S_TOK * D_MODEL];
__device__ __half g_m1 [S_TOK * D_MLP];
__device__ __half g_Qh [H_HEADS * S_TOK * HD];   // fp16, pre-scaled by 0.125
__device__ __half g_Kh [H_HEADS * S_TOK * HD];
__device__ __half g_Vt [H_HEADS * HD * S_TOK];   // TRANSPOSED: [head][dim][seq]
__device__ float  g_x2 [S_TOK * D_MODEL];
// fp16 weights (converted once per launch)
__device__ __half g_wq [3 * D_MODEL * D_MODEL];
__device__ __half g_wo [D_MODEL * D_MODEL];
__device__ __half g_w1 [D_MLP * D_MODEL];
__device__ __half g_w2 [D_MODEL * D_MLP];

// ---------------------------------------------------------------------------
// fp32 -> fp16 convert: all four weight arrays in ONE kernel
// ---------------------------------------------------------------------------
#define N4Q (3 * D_MODEL * D_MODEL / 4)
#define N4O (D_MODEL * D_MODEL / 4)
#define N4M (D_MLP * D_MODEL / 4)
#define N4TOT (N4Q + N4O + N4M + N4M)

__global__ void f2h_all(const float* __restrict__ wq, const float* __restrict__ wo,
                        const float* __restrict__ w1, const float* __restrict__ w2) {
    int i = blockIdx.x * blockDim.x + threadIdx.x;
    if (i >= N4TOT) return;
    const float* src;
    __half* dst;
    int off;
    if (i < N4Q)                  { src = wq; dst = g_wq; off = i; }
    else if (i < N4Q + N4O)       { src = wo; dst = g_wo; off = i - N4Q; }
    else if (i < N4Q + N4O + N4M) { src = w1; dst = g_w1; off = i - N4Q - N4O; }
    else                          { src = w2; dst = g_w2; off = i - N4Q - N4O - N4M; }
    float4 v = ((const float4*)src)[off];
    __half2 h0 = __floats2half2_rn(v.x, v.y);
    __half2 h1 = __floats2half2_rn(v.z, v.w);
    ((__half2*)dst)[2 * off]     = h0;
    ((__half2*)dst)[2 * off + 1] = h1;
}

// ---------------------------------------------------------------------------
// adaLN
// ---------------------------------------------------------------------------
__global__ void adaln_kernel(const float* __restrict__ c,
                             const float* __restrict__ W,
                             const float* __restrict__ b) {
    __shared__ float cs[COND];
    int tid = threadIdx.x;
    if (tid < COND) cs[tid] = c[tid];
    __syncthreads();
    int i = blockIdx.x * blockDim.x + tid;
    if (i >= 6 * D_MODEL) return;
    const float* w = W + (size_t)i * COND;
    float acc = 0.f;
#pragma unroll 8
    for (int j = 0; j < COND; j++) acc += w[j] * cs[j];
    g_mods[i] = acc + b[i];
}

// ---------------------------------------------------------------------------
// LayerNorm + modulate -> fp16 output
// ---------------------------------------------------------------------------
__inline__ __device__ float warp_reduce_sum(float v) {
#pragma unroll
    for (int o = 16; o > 0; o >>= 1) v += __shfl_xor_sync(0xffffffffu, v, o);
    return v;
}

__global__ void ln_mod_kernel(const float* __restrict__ X,
                              const float* __restrict__ w,
                              const float* __restrict__ sc,
                              const float* __restrict__ sh,
                              __half* __restrict__ out) {
    int row = blockIdx.x;
    const float4* x4 = (const float4*)(X + (size_t)row * D_MODEL);
    int tid = threadIdx.x;
    float4 v = x4[tid];
    float s  = v.x + v.y + v.z + v.w;
    float ss = v.x*v.x + v.y*v.y + v.z*v.z + v.w*v.w;
    __shared__ float red_s[8], red_ss[8];
    s  = warp_reduce_sum(s);
    ss = warp_reduce_sum(ss);
    int wid = tid >> 5, lid = tid & 31;
    if (lid == 0) { red_s[wid] = s; red_ss[wid] = ss; }
    __syncthreads();
    if (wid == 0) {
        float a = (lid < 8) ? red_s[lid]  : 0.f;
        float b = (lid < 8) ? red_ss[lid] : 0.f;
        a = warp_reduce_sum(a);
        b = warp_reduce_sum(b);
        if (lid == 0) { red_s[0] = a; red_ss[0] = b; }
    }
    __syncthreads();
    float mu  = red_s[0] * (1.f / D_MODEL);
    float var = red_ss[0] * (1.f / D_MODEL) - mu * mu;
    float inv = rsqrtf(var + 1e-5f);
    int d0 = tid * 4;
    float vv[4] = {v.x, v.y, v.z, v.w};
    float o[4];
#pragma unroll
    for (int i = 0; i < 4; i++) {
        int d = d0 + i;
        o[i] = (vv[i] - mu) * inv * w[d] * (1.f + sc[d]) + sh[d];
    }
    __half2 h0 = __floats2half2_rn(o[0], o[1]);
    __half2 h1 = __floats2half2_rn(o[2], o[3]);
    *(__half2*)&out[(size_t)row * D_MODEL + d0]     = h0;
    *(__half2*)&out[(size_t)row * D_MODEL + d0 + 2] = h1;
}

// ---------------------------------------------------------------------------
// Common PTX helpers
// ---------------------------------------------------------------------------
__device__ __forceinline__ float gelu_tanh(float x) {
    float x3 = x * x * x;
    return 0.5f * x * (1.f + tanhf(0.7978845608028654f * (x + 0.044715f * x3)));
}

__device__ __forceinline__ void cp16(void* dst, const void* src) {
    unsigned d = (unsigned)__cvta_generic_to_shared(dst);
    asm volatile("cp.async.cg.shared.global [%0], [%1], 16;\n" :: "r"(d), "l"(src));
}

__device__ __forceinline__ void ldsm4(unsigned& r0, unsigned& r1, unsigned& r2, unsigned& r3,
                                      const __half* p) {
    unsigned a = (unsigned)__cvta_generic_to_shared(p);
    asm volatile("ldmatrix.sync.aligned.m8n8.x4.shared.b16 {%0,%1,%2,%3}, [%4];\n"
                 : "=r"(r0), "=r"(r1), "=r"(r2), "=r"(r3) : "r"(a));
}

__device__ __forceinline__ void mma_fp16(float* c, const unsigned* a, const unsigned* b) {
    asm volatile(
        "mma.sync.aligned.m16n8k16.row.col.f32.f16.f16.f32 "
        "{%0,%1,%2,%3}, {%4,%5,%6,%7}, {%8,%9}, {%0,%1,%2,%3};\n"
        : "+f"(c[0]), "+f"(c[1]), "+f"(c[2]), "+f"(c[3])
        : "r"(a[0]), "r"(a[1]), "r"(a[2]), "r"(a[3]), "r"(b[0]), "r"(b[1]));
}

__device__ __forceinline__ unsigned packp(float x, float y) {
    __half2 h = __floats2half2_rn(x, y);
    return *(unsigned*)&h;
}

// ---------------------------------------------------------------------------
// FP16 GEMM: R9 shape (CTA 128x128, 256 thr, 8 warps 4x2, warp 32x64) with
// BK=64 stages: rows of 64 halves (128B), swizzle ch' = ch ^ (row & 7)
// (the attn-verified pattern), 3-stage cp.async ring, ONE barrier per 64-k.
// EPI: 0 qkv+rope, 1 gate*acc+res fp32, 2 gelu(acc+bias) fp16,
//      3 gate*(acc+bias)+res fp32
// ---------------------------------------------------------------------------
#define STG_H  (128 * 64)                // halves per operand per stage (16KB)
#define STG_SZ (2 * STG_H)               // A + B
#define GSMEM  (3 * STG_SZ * 2)          // 98304 bytes

template<int EPI>
__global__ void __launch_bounds__(256, 2)
gemm16(const __half* __restrict__ A, const __half* __restrict__ B,
       void* __restrict__ Cout, int M, int N, int K,
       const float* __restrict__ bias, const float* __restrict__ gate,
       const float* __restrict__ res,
       const float* __restrict__ cosT, const float* __restrict__ sinT,
       __half* __restrict__ Qp, __half* __restrict__ Kp, __half* __restrict__ Vtp) {
    extern __shared__ __align__(128) __half smem[];

    const int m0 = blockIdx.y * 128;
    const int n0 = blockIdx.x * 128;
    const int tid  = threadIdx.x;
    const int lane = tid & 31;
    const int warp = tid >> 5;
    const int wm = (warp >> 1) * 32;     // 0,32,64,96
    const int wn = (warp & 1) * 64;      // 0,64
    const int g  = lane >> 2;
    const int tg = lane & 3;

    float acc[2][8][4] = {};
    const int nT = K / 64;

    const int lrow = lane & 7;
    const int a_r8 = ((lane >> 3) & 1) * 8;
    const int a_cb = (lane >> 4) & 1;
    const int b_r8 = ((lane >> 4) & 1) * 8;
    const int b_cb = (lane >> 3) & 1;

    auto issue = [&](int b, int k0) {
        __half* sA = smem + b * STG_SZ;
        __half* sB = sA + STG_H;
#pragma unroll
        for (int i = 0; i < 4; i++) {
            int idx = tid + i * 256;             // 0..1023
            int row = idx >> 3, ch = idx & 7;
            int sw  = (ch ^ (row & 7)) * 8;
            cp16(&sA[row * 64 + sw], &A[(size_t)(m0 + row) * K + k0 + ch * 8]);
        }
#pragma unroll
        for (int i = 0; i < 4; i++) {
            int idx = tid + i * 256;
            int row = idx >> 3, ch = idx & 7;
            int sw  = (ch ^ (row & 7)) * 8;
            cp16(&sB[row * 64 + sw], &B[(size_t)(n0 + row) * K + k0 + ch * 8]);
        }
        asm volatile("cp.async.commit_group;\n");
    };

    issue(0, 0);
    if (nT > 1) issue(1, 64);

    for (int t = 0; t < nT; t++) {
        if (t + 1 < nT) asm volatile("cp.async.wait_group 1;\n");
        else            asm volatile("cp.async.wait_group 0;\n");
        __syncthreads();   // tile t ready; licenses overwrite of buf (t+2)%3
        if (t + 2 < nT) issue((t + 2) % 3, (t + 2) * 64);

        const __half* sA = smem + (t % 3) * STG_SZ;
        const __half* sB = sA + STG_H;
#pragma unroll
        for (int kk = 0; kk < 4; kk++) {
            unsigned af[2][4], bf[8][2];
#pragma unroll
            for (int i = 0; i < 2; i++) {
                int mr = wm + i * 16 + lrow + a_r8;
                int ch = 2 * kk + a_cb;
                int sw = ch ^ (mr & 7);
                ldsm4(af[i][0], af[i][1], af[i][2], af[i][3], &sA[mr * 64 + sw * 8]);
            }
#pragma unroll
            for (int jp = 0; jp < 4; jp++) {
                int nr = wn + jp * 16 + lrow + b_r8;
                int ch = 2 * kk + b_cb;
                int sw = ch ^ (nr & 7);
                ldsm4(bf[2*jp][0], bf[2*jp][1], bf[2*jp+1][0], bf[2*jp+1][1],
                      &sB[nr * 64 + sw * 8]);
            }
#pragma unroll
            for (int i = 0; i < 2; i++)
#pragma unroll
                for (int j = 0; j < 8; j++)
                    mma_fp16(acc[i][j], af[i], bf[j]);
        }
    }

    // ---------------- epilogues ----------------
    if (EPI == 0) {
        int colBlock = n0 + wn;
        int qidx = colBlock >> 10;
        int head = (colBlock & 1023) >> 6;
#pragma unroll
        for (int i = 0; i < 2; i++) {
#pragma unroll
            for (int hh = 0; hh < 2; hh++) {
                int row = m0 + wm + i * 16 + g + hh * 8;
                int p = row & (N_TOK - 1);
#pragma unroll
                for (int j = 0; j < 4; j++) {
                    float o1[2], o2[2];
#pragma unroll
                    for (int cc = 0; cc < 2; cc++) {
                        int d = j * 8 + tg * 2 + cc;
                        float x1 = acc[i][j][hh * 2 + cc];
                        float x2 = acc[i][j + 4][hh * 2 + cc];
                        float cs = cosT[p * 32 + d];
                        float sn = sinT[p * 32 + d];
                        o1[cc] = x1 * cs - x2 * sn;
                        o2[cc] = x2 * cs + x1 * sn;
                    }
                    int d0 = j * 8 + tg * 2;
                    if (qidx == 0) {
                        __half* dst = Qp + ((size_t)head * S_TOK + row) * HD;
                        *(__half2*)&dst[d0]      = __floats2half2_rn(o1[0]*0.125f, o1[1]*0.125f);
                        *(__half2*)&dst[d0 + 32] = __floats2half2_rn(o2[0]*0.125f, o2[1]*0.125f);
                    } else if (qidx == 1) {
                        __half* dst = Kp + ((size_t)head * S_TOK + row) * HD;
                        *(__half2*)&dst[d0]      = __floats2half2_rn(o1[0], o1[1]);
                        *(__half2*)&dst[d0 + 32] = __floats2half2_rn(o2[0], o2[1]);
                    } else {
                        __half* dst = Vtp + (size_t)head * HD * S_TOK;
                        dst[(size_t)(d0)      * S_TOK + row] = __float2half(o1[0]);
                        dst[(size_t)(d0 + 1)  * S_TOK + row] = __float2half(o1[1]);
                        dst[(size_t)(d0 + 32) * S_TOK + row] = __float2half(o2[0]);
                        dst[(size_t)(d0 + 33) * S_TOK + row] = __float2half(o2[1]);
                    }
                }
            }
        }
        return;
    }

#pragma unroll
    for (int i = 0; i < 2; i++) {
        int row0 = m0 + wm + i * 16 + g;
#pragma unroll
        for (int j = 0; j < 8; j++) {
            int col = n0 + wn + j * 8 + tg * 2;
#pragma unroll
            for (int hh = 0; hh < 2; hh++) {
                int row = row0 + hh * 8;
                float v0 = acc[i][j][hh * 2 + 0];
                float v1 = acc[i][j][hh * 2 + 1];
                if (EPI == 1) {
                    float* C = (float*)Cout;
                    C[(size_t)row * N + col]     = gate[col] * v0 + res[(size_t)row * N + col];
                    C[(size_t)row * N + col + 1] = gate[col+1] * v1 + res[(size_t)row * N + col + 1];
                } else if (EPI == 2) {
                    __half* C = (__half*)Cout;
                    __half2 hv = __floats2half2_rn(gelu_tanh(v0 + bias[col]),
                                                   gelu_tanh(v1 + bias[col + 1]));
                    *(__half2*)&C[(size_t)row * N + col] = hv;
                } else {
                    float* C = (float*)Cout;
                    C[(size_t)row * N + col]     = gate[col] * (v0 + bias[col]) + res[(size_t)row * N + col];
                    C[(size_t)row * N + col + 1] = gate[col+1] * (v1 + bias[col+1]) + res[(size_t)row * N + col + 1];
                }
            }
        }
    }
}

// ---------------------------------------------------------------------------
// Paired-block FP16 MMA attention.
// CTA = (j, head): handles noisy block j (rows 16j..16j+15) AND clean block j
// (rows 1024+16j..+15). They share the clean prefix [1024, 1024+16j).
// Tiles: nP = ceil(16(j+1)/64) prefix tiles over [1024, 1024+16(j+1)), then
// one diag tile at k0 = 16j (valid 16 keys for noisy rows only).
// Masks are whole 8-key blocks (all boundaries are multiples of 16).
// NaN guard: nmSafe=0 when running max still -inf (all-masked row group).
// ---------------------------------------------------------------------------
__global__ void __launch_bounds__(128)
attn_kernel(__half* __restrict__ O) {
    __shared__ __half Qs[32 * 64];
    __shared__ __half Ks[2][64 * 64];
    __shared__ __half Vs[2][64 * 64];   // Vt tile: [dim][key]

    const int j = blockIdx.x;           // 0..63
    const int h = blockIdx.y;
    const int t = threadIdx.x;
    const int lane = t & 31;
    const int warp = t >> 5;
    const int g  = lane >> 2;
    const int tg = lane & 3;
    const int lrow = lane & 7;
    const int a_r8 = ((lane >> 3) & 1) * 8;
    const int a_cb = (lane >> 4) & 1;
    const int b_r8 = ((lane >> 4) & 1) * 8;
    const int b_cb = (lane >> 3) & 1;

    const int q0n = j * 16;
    const int q0c = N_TOK + j * 16;
    const __half* Qg = g_Qh + (size_t)h * S_TOK * HD;
    const __half* Kg = g_Kh + (size_t)h * S_TOK * HD;
    const __half* Vg = g_Vt + (size_t)h * HD * S_TOK;

    const int nP = (j + 4) >> 2;        // ceil((j+1)/4)
    const int nT = nP + 1;

    auto tile_k0 = [&](int ti) {
        return (ti < nP) ? (N_TOK + 64 * ti) : (16 * j);
    };

    // Q: 32 rows (16 noisy + 16 clean) x 8 chunks = 256 cp.async
    {
#pragma unroll
        for (int i = 0; i < 2; i++) {
            int idx = t + i * 128;
            int row = idx >> 3, ch = idx & 7;
            int rq  = (row < 16) ? (q0n + row) : (q0c + row - 16);
            cp16(&Qs[row * 64 + (ch ^ (row & 7)) * 8], &Qg[(size_t)rq * HD + ch * 8]);
        }
    }
    auto issueKV = [&](int b, int k0) {
#pragma unroll
        for (int i = 0; i < 4; i++) {
            int idx = t + i * 128;
            int row = idx >> 3, ch = idx & 7;
            int sw  = (ch ^ (row & 7)) * 8;
            int src = min(k0 + row, S_TOK - 1);
            cp16(&Ks[b][row * 64 + sw], &Kg[(size_t)src * HD + ch * 8]);
            cp16(&Vs[b][row * 64 + sw], &Vg[(size_t)row * S_TOK + k0 + ch * 8]);
        }
        asm volatile("cp.async.commit_group;\n");
    };
    issueKV(0, tile_k0(0));

    unsigned aq[2][4][4];                 // [row-group][kb]
    float Oacc[2][2][4] = {};             // [row-group][nb2]
    float mr[2][2] = {{-INFINITY,-INFINITY},{-INFINITY,-INFINITY}};
    float lr[2][2] = {};

    for (int ti = 0; ti < nT; ti++) {
        asm volatile("cp.async.wait_group 0;\n");
        __syncthreads();
        if (ti == 0) {
#pragma unroll
            for (int rg = 0; rg < 2; rg++)
#pragma unroll
                for (int kb = 0; kb < 4; kb++) {
                    int r  = rg * 16 + lrow + a_r8;
                    int ch = 2 * kb + a_cb;
                    ldsm4(aq[rg][kb][0], aq[rg][kb][1], aq[rg][kb][2], aq[rg][kb][3],
                          &Qs[r * 64 + (ch ^ (r & 7)) * 8]);
                }
        }
        if (ti + 1 < nT) issueKV((ti + 1) & 1, tile_k0(ti + 1));

        const __half* sK = Ks[ti & 1];
        const __half* sV = Vs[ti & 1];
        int vN, vC;
        if (ti < nP) {
            int off = 64 * ti;
            vN = max(0, min(64, 16 * j - off));
            vC = max(0, min(64, 16 * (j + 1) - off));
        } else { vN = 16; vC = 0; }

        // ---- scores: 32x64 (both row groups) ----
        float sc[2][8][4] = {};
#pragma unroll
        for (int kb = 0; kb < 4; kb++) {
            unsigned bf[8][2];
#pragma unroll
            for (int pr = 0; pr < 4; pr++) {
                int r  = pr * 16 + lrow + b_r8;
                int ch = 2 * kb + b_cb;
                ldsm4(bf[2*pr][0], bf[2*pr][1], bf[2*pr+1][0], bf[2*pr+1][1],
                      &sK[r * 64 + (ch ^ (r & 7)) * 8]);
            }
#pragma unroll
            for (int nb = 0; nb < 8; nb++) {
                mma_fp16(sc[0][nb], aq[0][kb], bf[nb]);
                mma_fp16(sc[1][nb], aq[1][kb], bf[nb]);
            }
        }

        unsigned ap[2][4][4];
#pragma unroll
        for (int rg = 0; rg < 2; rg++) {
            int v = rg ? vC : vN;
#pragma unroll
            for (int nb = 0; nb < 8; nb++)
                if (nb * 8 >= v) {
                    sc[rg][nb][0] = sc[rg][nb][1] = sc[rg][nb][2] = sc[rg][nb][3] = -INFINITY;
                }

            float mx0 = -INFINITY, mx1 = -INFINITY;
#pragma unroll
            for (int nb = 0; nb < 8; nb++) {
                mx0 = fmaxf(mx0, fmaxf(sc[rg][nb][0], sc[rg][nb][1]));
                mx1 = fmaxf(mx1, fmaxf(sc[rg][nb][2], sc[rg][nb][3]));
            }
            mx0 = fmaxf(mx0, __shfl_xor_sync(0xffffffffu, mx0, 1));
            mx0 = fmaxf(mx0, __shfl_xor_sync(0xffffffffu, mx0, 2));
            mx1 = fmaxf(mx1, __shfl_xor_sync(0xffffffffu, mx1, 1));
            mx1 = fmaxf(mx1, __shfl_xor_sync(0xffffffffu, mx1, 2));

            float nm0 = fmaxf(mr[rg][0], mx0), nm1 = fmaxf(mr[rg][1], mx1);
            float nms0 = (nm0 == -INFINITY) ? 0.f : nm0;
            float nms1 = (nm1 == -INFINITY) ? 0.f : nm1;
            float c0 = __expf(mr[rg][0] - nms0), c1 = __expf(mr[rg][1] - nms1);
            float ts0 = 0.f, ts1 = 0.f;
#pragma unroll
            for (int nb = 0; nb < 8; nb++) {
                sc[rg][nb][0] = __expf(sc[rg][nb][0] - nms0);
                sc[rg][nb][1] = __expf(sc[rg][nb][1] - nms0);
                sc[rg][nb][2] = __expf(sc[rg][nb][2] - nms1);
                sc[rg][nb][3] = __expf(sc[rg][nb][3] - nms1);
                ts0 += sc[rg][nb][0] + sc[rg][nb][1];
                ts1 += sc[rg][nb][2] + sc[rg][nb][3];
            }
            ts0 += __shfl_xor_sync(0xffffffffu, ts0, 1);
            ts0 += __shfl_xor_sync(0xffffffffu, ts0, 2);
            ts1 += __shfl_xor_sync(0xffffffffu, ts1, 1);
            ts1 += __shfl_xor_sync(0xffffffffu, ts1, 2);
            lr[rg][0] = lr[rg][0] * c0 + ts0;  mr[rg][0] = nm0;
            lr[rg][1] = lr[rg][1] * c1 + ts1;  mr[rg][1] = nm1;

#pragma unroll
            for (int nb2 = 0; nb2 < 2; nb2++) {
                Oacc[rg][nb2][0] *= c0; Oacc[rg][nb2][1] *= c0;
                Oacc[rg][nb2][2] *= c1; Oacc[rg][nb2][3] *= c1;
            }

#pragma unroll
            for (int kb2 = 0; kb2 < 4; kb2++) {
                ap[rg][kb2][0] = packp(sc[rg][2*kb2][0],   sc[rg][2*kb2][1]);
                ap[rg][kb2][1] = packp(sc[rg][2*kb2][2],   sc[rg][2*kb2][3]);
                ap[rg][kb2][2] = packp(sc[rg][2*kb2+1][0], sc[rg][2*kb2+1][1]);
                ap[rg][kb2][3] = packp(sc[rg][2*kb2+1][2], sc[rg][2*kb2+1][3]);
            }
        }

        // ---- PV: this warp's 16 output dims, both row groups ----
#pragma unroll
        for (int kb2 = 0; kb2 < 4; kb2++) {
            unsigned bv0[2], bv1[2];
            int r  = warp * 16 + lrow + b_r8;
            int ch = 2 * kb2 + b_cb;
            ldsm4(bv0[0], bv0[1], bv1[0], bv1[1],
                  &sV[r * 64 + (ch ^ (r & 7)) * 8]);
            mma_fp16(Oacc[0][0], ap[0][kb2], bv0);
            mma_fp16(Oacc[0][1], ap[0][kb2], bv1);
            mma_fp16(Oacc[1][0], ap[1][kb2], bv0);
            mma_fp16(Oacc[1][1], ap[1][kb2], bv1);
        }
        __syncthreads();
    }

    // ---- epilogue: both row groups ----
#pragma unroll
    for (int rg = 0; rg < 2; rg++) {
        float inv0 = 1.f / lr[rg][0], inv1 = 1.f / lr[rg][1];
        int base = rg ? q0c : q0n;
        int row0 = base + g, row1 = base + g + 8;
#pragma unroll
        for (int nb2 = 0; nb2 < 2; nb2++) {
            int col = h * HD + warp * 16 + nb2 * 8 + tg * 2;
            *(__half2*)&O[(size_t)row0 * D_MODEL + col] =
                __floats2half2_rn(Oacc[rg][nb2][0] * inv0, Oacc[rg][nb2][1] * inv0);
            *(__half2*)&O[(size_t)row1 * D_MODEL + col] =
                __floats2half2_rn(Oacc[rg][nb2][2] * inv1, Oacc[rg][nb2][3] * inv1);
        }
    }
}

// ---------------------------------------------------------------------------
// kernel_launch
// ---------------------------------------------------------------------------
extern "C" void kernel_launch(void* const* d_in, const int* in_sizes, int n_in,
                              void* d_out, int out_size) {
    const float* x          = (const float*)d_in[0];
    const float* c          = (const float*)d_in[1];
    const float* cosT       = (const float*)d_in[2];
    const float* sinT       = (const float*)d_in[3];
    const float* norm1_w    = (const float*)d_in[4];
    const float* qkv_w      = (const float*)d_in[5];
    const float* attn_out_w = (const float*)d_in[6];
    const float* norm2_w    = (const float*)d_in[7];
    const float* mlp_w1     = (const float*)d_in[8];
    const float* mlp_b1     = (const float*)d_in[9];
    const float* mlp_w2     = (const float*)d_in[10];
    const float* mlp_b2     = (const float*)d_in[11];
    const float* adaLN_w    = (const float*)d_in[12];
    const float* adaLN_b    = (const float*)d_in[13];
    float* out = (float*)d_out;

    float *mods, *x2;
    __half *h, *h2, *Oh, *m1, *Qp, *Kp, *Vtp, *wq, *wo, *w1, *w2;
    cudaGetSymbolAddress((void**)&mods, g_mods);
    cudaGetSymbolAddress((void**)&h,    g_h);
    cudaGetSymbolAddress((void**)&h2,   g_h2);
    cudaGetSymbolAddress((void**)&Oh,   g_Oh);
    cudaGetSymbolAddress((void**)&m1,   g_m1);
    cudaGetSymbolAddress((void**)&Qp,   g_Qh);
    cudaGetSymbolAddress((void**)&Kp,   g_Kh);
    cudaGetSymbolAddress((void**)&Vtp,  g_Vt);
    cudaGetSymbolAddress((void**)&x2,   g_x2);
    cudaGetSymbolAddress((void**)&wq,   g_wq);
    cudaGetSymbolAddress((void**)&wo,   g_wo);
    cudaGetSymbolAddress((void**)&w1,   g_w1);
    cudaGetSymbolAddress((void**)&w2,   g_w2);

    const float* sh_msa = mods + 0 * D_MODEL;
    const float* sc_msa = mods + 1 * D_MODEL;
    const float* g_msa  = mods + 2 * D_MODEL;
    const float* sh_mlp = mods + 3 * D_MODEL;
    const float* sc_mlp = mods + 4 * D_MODEL;
    const float* g_mlp  = mods + 5 * D_MODEL;

    static bool attr_set = false;
    if (!attr_set) {
        cudaFuncSetAttribute(gemm16<0>, cudaFuncAttributeMaxDynamicSharedMemorySize, GSMEM);
        cudaFuncSetAttribute(gemm16<1>, cudaFuncAttributeMaxDynamicSharedMemorySize, GSMEM);
        cudaFuncSetAttribute(gemm16<2>, cudaFuncAttributeMaxDynamicSharedMemorySize, GSMEM);
        cudaFuncSetAttribute(gemm16<3>, cudaFuncAttributeMaxDynamicSharedMemorySize, GSMEM);
        attr_set = true;
    }

    f2h_all<<<(N4TOT + 255) / 256, 256>>>(qkv_w, attn_out_w, mlp_w1, mlp_w2);

    adaln_kernel<<<(6 * D_MODEL + 127) / 128, 128>>>(c, adaLN_w, adaLN_b);

    ln_mod_kernel<<<S_TOK, 256>>>(x, norm1_w, sc_msa, sh_msa, h);

    gemm16<0><<<dim3(3 * D_MODEL / 128, S_TOK / 128), 256, GSMEM>>>(
        h, wq, nullptr, S_TOK, 3 * D_MODEL, D_MODEL,
        nullptr, nullptr, nullptr, cosT, sinT, Qp, Kp, Vtp);

    attn_kernel<<<dim3(N_TOK / 16, H_HEADS), 128>>>(Oh);

    gemm16<1><<<dim3(D_MODEL / 128, S_TOK / 128), 256, GSMEM>>>(
        Oh, wo, x2, S_TOK, D_MODEL, D_MODEL,
        nullptr, g_msa, x, nullptr, nullptr, nullptr, nullptr, nullptr);

    ln_mod_kernel<<<S_TOK, 256>>>(x2, norm2_w, sc_mlp, sh_mlp, h2);

    gemm16<2><<<dim3(D_MLP / 128, S_TOK / 128), 256, GSMEM>>>(
        h2, w1, m1, S_TOK, D_MLP, D_MODEL,
        mlp_b1, nullptr, nullptr, nullptr, nullptr, nullptr, nullptr, nullptr);

    gemm16<3><<<dim3(D_MODEL / 128, S_TOK / 128), 256, GSMEM>>>(
        m1, w2, out, S_TOK, D_MODEL, D_MLP,
        mlp_b2, g_mlp, x2, nullptr, nullptr, nullptr, nullptr, nullptr);
}